// round 1
// baseline (speedup 1.0000x reference)
#include <cuda_runtime.h>

#define S_PER_BLK 4
#define T_STEPS   1024
#define H_DIM     64
#define G_DIM     256   // 4*H
#define D_DIM     4
#define NTHREADS  256

typedef unsigned long long ull;

// ---- fast activations (err ~1e-6, well under 1e-3 budget) ----
__device__ __forceinline__ float fsig(float x) {
    float e = __expf(-x);          // ex2.approx based
    float d = 1.0f + e;
    float r;
    asm("rcp.approx.f32 %0, %1;" : "=f"(r) : "f"(d));
    return r;
}
__device__ __forceinline__ float ftanh(float x) {
    return __fmaf_rn(2.0f, fsig(2.0f * x), -1.0f);
}

// ---- packed f32x2 fma (sm_100+) ----
__device__ __forceinline__ void fma2(ull& d, ull a, ull b, ull c) {
    asm("fma.rn.f32x2 %0, %1, %2, %3;" : "=l"(d) : "l"(a), "l"(b), "l"(c));
}
__device__ __forceinline__ float fold2(ull a) {
    float lo, hi;
    asm("mov.b64 {%0,%1}, %2;" : "=f"(lo), "=f"(hi) : "l"(a));
    return lo + hi;
}

// Dynamic smem layout (floats):
//   xs  : S*T*D        = 16384
//   h1s : S*H          = 256
//   h2s : S*H          = 256
//   ga0 : S*G          = 1024
//   ga1 : S*G          = 1024
// total = 18944 floats = 75776 bytes

__global__ __launch_bounds__(NTHREADS, 1)
void lstm_fused_kernel(const float* __restrict__ x,
                       const float* __restrict__ W_ih0,
                       const float* __restrict__ W_hh0,
                       const float* __restrict__ b0,
                       const float* __restrict__ W_ih1,
                       const float* __restrict__ W_hh1,
                       const float* __restrict__ b1,
                       const float* __restrict__ W_fc1,
                       const float* __restrict__ b_fc1,
                       const float* __restrict__ W_fc2,
                       const float* __restrict__ b_fc2,
                       float* __restrict__ out)
{
    extern __shared__ float sm[];
    float* xs  = sm;                                   // [S][T][D]
    float* h1s = sm + S_PER_BLK * T_STEPS * D_DIM;     // [S][H]
    float* h2s = h1s + S_PER_BLK * H_DIM;              // [S][H]
    float* ga0 = h2s + S_PER_BLK * H_DIM;              // [S][G]
    float* ga1 = ga0 + S_PER_BLK * G_DIM;              // [S][G]

    const int g   = threadIdx.x;        // gate index 0..255
    const int bb  = blockIdx.x * S_PER_BLK;

    // ---- load this thread's weight rows into registers (packed as f32x2) ----
    ull w0p[32], w1p[32], w2p[32];
    {
        const ull* p0 = (const ull*)(W_hh0 + g * H_DIM);
        const ull* p1 = (const ull*)(W_ih1 + g * H_DIM);
        const ull* p2 = (const ull*)(W_hh1 + g * H_DIM);
        #pragma unroll
        for (int i = 0; i < 32; i++) {
            w0p[i] = p0[i];
            w1p[i] = p1[i];
            w2p[i] = p2[i];
        }
    }
    float wi0[D_DIM];
    #pragma unroll
    for (int d = 0; d < D_DIM; d++) wi0[d] = W_ih0[g * D_DIM + d];
    const float bias0 = b0[g];
    const float bias1 = b1[g];

    // ---- stage x for the S samples into smem (one-time, coalesced) ----
    {
        const float4* gx = (const float4*)(x + (size_t)bb * T_STEPS * D_DIM);
        float4*       sx = (float4*)xs;
        #pragma unroll 4
        for (int i = g; i < S_PER_BLK * T_STEPS; i += NTHREADS) sx[i] = gx[i];
    }
    for (int i = g; i < S_PER_BLK * H_DIM; i += NTHREADS) { h1s[i] = 0.f; h2s[i] = 0.f; }

    float c1r[S_PER_BLK], c2r[S_PER_BLK];
    #pragma unroll
    for (int s = 0; s < S_PER_BLK; s++) { c1r[s] = 0.f; c2r[s] = 0.f; }

    __syncthreads();

    const bool is_tanh = (g >= 2 * H_DIM) && (g < 3 * H_DIM);  // gate 'g' chunk

    for (int t = 0; t < T_STEPS; t++) {
        // ---------- layer 0 gates: pre = b0 + x_t·Wih0_row + h1·Whh0_row ----------
        {
            ull acc[S_PER_BLK];
            #pragma unroll
            for (int s = 0; s < S_PER_BLK; s++) acc[s] = 0ULL;
            #pragma unroll
            for (int k = 0; k < 32; k++) {
                #pragma unroll
                for (int s = 0; s < S_PER_BLK; s++) {
                    ull hv = ((const ull*)(h1s + s * H_DIM))[k];   // LDS.64 broadcast
                    fma2(acc[s], w0p[k], hv, acc[s]);
                }
            }
            #pragma unroll
            for (int s = 0; s < S_PER_BLK; s++) {
                const float4 xv = ((const float4*)xs)[s * T_STEPS + t];
                float pre = fold2(acc[s]) + bias0;
                pre = __fmaf_rn(xv.x, wi0[0], pre);
                pre = __fmaf_rn(xv.y, wi0[1], pre);
                pre = __fmaf_rn(xv.z, wi0[2], pre);
                pre = __fmaf_rn(xv.w, wi0[3], pre);
                ga0[s * G_DIM + g] = is_tanh ? ftanh(pre) : fsig(pre);
            }
        }
        __syncthreads();  // B1

        // ---------- layer 0 state update (64 unit threads) ----------
        if (g < H_DIM) {
            #pragma unroll
            for (int s = 0; s < S_PER_BLK; s++) {
                float iv = ga0[s * G_DIM + g];
                float fv = ga0[s * G_DIM + g + H_DIM];
                float gv = ga0[s * G_DIM + g + 2 * H_DIM];
                float ov = ga0[s * G_DIM + g + 3 * H_DIM];
                float c  = __fmaf_rn(fv, c1r[s], iv * gv);
                c1r[s] = c;
                h1s[s * H_DIM + g] = ov * ftanh(c);
            }
        }
        __syncthreads();  // B2

        // ---------- layer 1 gates: pre = b1 + h1·Wih1_row + h2·Whh1_row ----------
        {
            ull acc[S_PER_BLK];
            #pragma unroll
            for (int s = 0; s < S_PER_BLK; s++) acc[s] = 0ULL;
            #pragma unroll
            for (int k = 0; k < 32; k++) {
                #pragma unroll
                for (int s = 0; s < S_PER_BLK; s++) {
                    ull hv = ((const ull*)(h1s + s * H_DIM))[k];
                    fma2(acc[s], w1p[k], hv, acc[s]);
                }
            }
            #pragma unroll
            for (int k = 0; k < 32; k++) {
                #pragma unroll
                for (int s = 0; s < S_PER_BLK; s++) {
                    ull hv = ((const ull*)(h2s + s * H_DIM))[k];
                    fma2(acc[s], w2p[k], hv, acc[s]);
                }
            }
            #pragma unroll
            for (int s = 0; s < S_PER_BLK; s++) {
                float pre = fold2(acc[s]) + bias1;
                ga1[s * G_DIM + g] = is_tanh ? ftanh(pre) : fsig(pre);
            }
        }
        __syncthreads();  // B3

        // ---------- layer 1 state update ----------
        if (g < H_DIM) {
            #pragma unroll
            for (int s = 0; s < S_PER_BLK; s++) {
                float iv = ga1[s * G_DIM + g];
                float fv = ga1[s * G_DIM + g + H_DIM];
                float gv = ga1[s * G_DIM + g + 2 * H_DIM];
                float ov = ga1[s * G_DIM + g + 3 * H_DIM];
                float c  = __fmaf_rn(fv, c2r[s], iv * gv);
                c2r[s] = c;
                h2s[s * H_DIM + g] = ov * ftanh(c);
            }
        }
        // no barrier needed here: next-iter B1 orders h2s/ga1 before their next use
    }
    __syncthreads();  // final h2s visible to everyone

    // ---------- classifier: relu(h2 @ Wfc1^T + b1) @ Wfc2^T + b2 -> sigmoid ----------
    if (g < S_PER_BLK * 32) {
        int s = g >> 5, j = g & 31;
        float a = b_fc1[j];
        #pragma unroll
        for (int k = 0; k < H_DIM; k++)
            a = __fmaf_rn(h2s[s * H_DIM + k], W_fc1[j * H_DIM + k], a);
        ga0[s * 32 + j] = fmaxf(a, 0.f);   // reuse ga0 as hid[S][32]
    }
    __syncthreads();
    if (g < S_PER_BLK) {
        float a = b_fc2[0];
        #pragma unroll
        for (int j = 0; j < 32; j++)
            a = __fmaf_rn(ga0[g * 32 + j], W_fc2[j], a);
        out[bb + g] = fsig(a);
    }
}

extern "C" void kernel_launch(void* const* d_in, const int* in_sizes, int n_in,
                              void* d_out, int out_size)
{
    const float* x     = (const float*)d_in[0];
    const float* W_ih0 = (const float*)d_in[1];
    const float* W_hh0 = (const float*)d_in[2];
    const float* b0    = (const float*)d_in[3];
    const float* W_ih1 = (const float*)d_in[4];
    const float* W_hh1 = (const float*)d_in[5];
    const float* b1    = (const float*)d_in[6];
    const float* W_fc1 = (const float*)d_in[7];
    const float* b_fc1 = (const float*)d_in[8];
    const float* W_fc2 = (const float*)d_in[9];
    const float* b_fc2 = (const float*)d_in[10];
    float* out = (float*)d_out;

    const size_t smem_bytes =
        (size_t)(S_PER_BLK * T_STEPS * D_DIM      // xs
                 + 2 * S_PER_BLK * H_DIM          // h1s, h2s
                 + 2 * S_PER_BLK * G_DIM)         // ga0, ga1
        * sizeof(float);

    cudaFuncSetAttribute(lstm_fused_kernel,
                         cudaFuncAttributeMaxDynamicSharedMemorySize,
                         (int)smem_bytes);

    const int nblocks = 512 / S_PER_BLK;   // 128
    lstm_fused_kernel<<<nblocks, NTHREADS, smem_bytes>>>(
        x, W_ih0, W_hh0, b0, W_ih1, W_hh1, b1,
        W_fc1, b_fc1, W_fc2, b_fc2, out);
}